// round 3
// baseline (speedup 1.0000x reference)
#include <cuda_runtime.h>
#include <cstdint>

// Problem dims
#define Vv 32000
#define Ee 128
#define Hh 128
#define Bb 32
#define Ss 32
#define RR 64                  // 64 fused rows: 0..31 teacher, 32..63 generation
static const int PRED_OFF = 2048;           // gen_x[1024] + gen_o[1024]
static const int PRED_N   = Bb * Ss * Vv;   // 32,768,000

// ---------------- persistent device scratch (no allocations allowed) -------
__device__ float               g_h[RR * Hh];
__device__ float               g_c[RR * Hh];
__device__ float               g_xg[Ss * Bb * 4 * Hh];  // teacher x-gates (with bias)
__device__ float               g_sumexp[Ss * RR];
__device__ unsigned long long  g_packmax[Ss * Bb];
__device__ float               g_invse[Ss * Bb];        // indexed by b*S + t
__device__ float               g_loss;                  // sum of logit at target

// ---------------- helpers --------------------------------------------------
__device__ __forceinline__ float sigm(float x) { return 1.0f / (1.0f + expf(-x)); }

__device__ __forceinline__ unsigned f2ord(float f) {
    unsigned u = __float_as_uint(f);
    return (u & 0x80000000u) ? ~u : (u | 0x80000000u);
}
__device__ __forceinline__ float ord2f(unsigned o) {
    return __uint_as_float((o & 0x80000000u) ? (o ^ 0x80000000u) : ~o);
}

__device__ __forceinline__ unsigned long long fma2(unsigned long long a,
                                                   unsigned long long b,
                                                   unsigned long long c) {
    unsigned long long d;
    asm("fma.rn.f32x2 %0, %1, %2, %3;" : "=l"(d) : "l"(a), "l"(b), "l"(c));
    return d;
}
__device__ __forceinline__ unsigned long long pack2(float w) {
    unsigned long long d;
    unsigned u = __float_as_uint(w);
    asm("mov.b64 %0, {%1, %1};" : "=l"(d) : "r"(u));
    return d;
}
__device__ __forceinline__ void unpack2(unsigned long long a, float& lo, float& hi) {
    unsigned l, h;
    asm("mov.b64 {%0, %1}, %2;" : "=r"(l), "=r"(h) : "l"(a));
    lo = __uint_as_float(l);
    hi = __uint_as_float(h);
}

// ---------------- prologue: teacher-forced x-gate projections --------------
// xg[t][b][g][j] = b_g[j] + emb[tok] . W_g[:,j],  tok = t==0 ? START : x[b][t-1]
__global__ void k_prologue(const int* __restrict__ x, const float* __restrict__ emb,
                           const float* __restrict__ Wi, const float* __restrict__ bi,
                           const float* __restrict__ Wf, const float* __restrict__ bf,
                           const float* __restrict__ Wog, const float* __restrict__ bog,
                           const float* __restrict__ Wc, const float* __restrict__ bc) {
    int p = blockIdx.x;            // p = t*32 + b
    int t = p >> 5, b = p & 31;
    int j = threadIdx.x;
    if (p == 0 && j == 0) g_loss = 0.0f;

    __shared__ float xe[Ee];
    int tok = (t == 0) ? 0 : x[b * Ss + (t - 1)];
    xe[j] = emb[tok * Ee + j];
    __syncthreads();

    float gi = bi[j], gf = bf[j], go = bog[j], gc = bc[j];
#pragma unroll 8
    for (int k = 0; k < Ee; ++k) {
        float xk = xe[k];
        gi += xk * Wi[k * Hh + j];
        gf += xk * Wf[k * Hh + j];
        go += xk * Wog[k * Hh + j];
        gc += xk * Wc[k * Hh + j];
    }
    float* o = g_xg + p * 4 * Hh;
    o[0 * Hh + j] = gi;
    o[1 * Hh + j] = gf;
    o[2 * Hh + j] = go;
    o[3 * Hh + j] = gc;
}

// ---------------- per-step LSTM cell (64 rows) -----------------------------
// Also: decodes previous step's argmax for gen rows (writes gen_x/gen_o[t-1]),
// and zero-inits this step's reduction accumulators.
__global__ void k_cell(int t, const float* __restrict__ emb,
                       const float* __restrict__ Wi, const float* __restrict__ Ui, const float* __restrict__ bi,
                       const float* __restrict__ Wf, const float* __restrict__ Uf, const float* __restrict__ bf,
                       const float* __restrict__ Wog, const float* __restrict__ Uog, const float* __restrict__ bog,
                       const float* __restrict__ Wc, const float* __restrict__ Uc, const float* __restrict__ bc,
                       float* __restrict__ out) {
    int r = blockIdx.x;            // 0..63
    int j = threadIdx.x;           // 0..127
    bool isgen = (r >= Bb);
    int b = isgen ? (r - Bb) : r;

    __shared__ float hsh[Hh];
    __shared__ float xe[Ee];

    if (j == 0) {
        g_sumexp[t * RR + r] = 0.0f;
        if (isgen) g_packmax[t * Bb + b] = 0ull;
    }

    float hprev = (t == 0) ? 0.0f : g_h[r * Hh + j];
    hsh[j] = hprev;

    float gi, gf, go, gc;
    if (isgen) {
        int tok = 0;
        if (t > 0) {
            unsigned long long key = g_packmax[(t - 1) * Bb + b];
            tok = (int)(0xFFFFFFFFu - (unsigned)(key & 0xFFFFFFFFull));
            if (j == 0) {
                float lg = ord2f((unsigned)(key >> 32));
                float se = g_sumexp[(t - 1) * RR + r];
                out[b * Ss + (t - 1)] = (float)tok;                 // gen_x
                out[Bb * Ss + b * Ss + (t - 1)] = expf(lg) / se;    // gen_o
            }
        }
        xe[j] = emb[tok * Ee + j];
        gi = bi[j]; gf = bf[j]; go = bog[j]; gc = bc[j];
        __syncthreads();
#pragma unroll 8
        for (int k = 0; k < Ee; ++k) {
            float xk = xe[k];
            gi += xk * Wi[k * Hh + j];
            gf += xk * Wf[k * Hh + j];
            go += xk * Wog[k * Hh + j];
            gc += xk * Wc[k * Hh + j];
        }
    } else {
        const float* xg = g_xg + (t * Bb + b) * 4 * Hh;
        gi = xg[j]; gf = xg[Hh + j]; go = xg[2 * Hh + j]; gc = xg[3 * Hh + j];
        __syncthreads();
    }

    if (t > 0) {
#pragma unroll 8
        for (int k = 0; k < Hh; ++k) {
            float hk = hsh[k];
            gi += hk * Ui[k * Hh + j];
            gf += hk * Uf[k * Hh + j];
            go += hk * Uog[k * Hh + j];
            gc += hk * Uc[k * Hh + j];
        }
    }

    float cprev = (t == 0) ? 0.0f : g_c[r * Hh + j];
    float ig = sigm(gi), fg = sigm(gf), og = sigm(go);
    float cn = fg * cprev + ig * tanhf(gc);
    float hn = og * tanhf(cn);
    g_h[r * Hh + j] = hn;
    g_c[r * Hh + j] = cn;
}

// ---------------- per-step output GEMM + reductions ------------------------
// logits[r][v] = h[r] . Wo[:,v] + bo[v] for all 64 rows.
// Teacher rows: logit stored into pred region (converted to prob at the end),
//   exp summed per row (atomicAdd), logit-at-target summed into g_loss.
// Gen rows: exp summed per row, packed (logit,idx) max per row (atomicMax).
#define KB_STEP(KK, WREG)                                                       \
    {                                                                           \
        const ulonglong2* hp = (const ulonglong2*)(&h_s[(KK)][0]);              \
        unsigned long long ww = pack2(WREG);                                    \
        _Pragma("unroll")                                                       \
        for (int p = 0; p < 16; ++p) {                                          \
            ulonglong2 hv = hp[p];                                              \
            acc[2 * p]     = fma2(hv.x, ww, acc[2 * p]);                        \
            acc[2 * p + 1] = fma2(hv.y, ww, acc[2 * p + 1]);                    \
        }                                                                       \
    }

__global__ void __launch_bounds__(128, 2)
k_big(int t, const int* __restrict__ x, const float* __restrict__ Wo,
      const float* __restrict__ bo, float* __restrict__ out) {
    __shared__ float h_s[Hh][68];   // transposed h, padded (68*4 % 16 == 0)
    __shared__ float wsum[4][RR];
    __shared__ unsigned long long wkey[4][Bb];
    __shared__ int tgt_s[Bb];

    int tid = threadIdx.x;
    int v = blockIdx.x * 128 + tid;

    for (int it = 0; it < RR; ++it)
        h_s[tid][it] = g_h[it * Hh + tid];   // coalesced read, transpose write
    if (tid < Bb) tgt_s[tid] = x[tid * Ss + t];
    __syncthreads();

    unsigned long long acc[32];
#pragma unroll
    for (int p = 0; p < 32; ++p) acc[p] = 0ull;

    const float* Wp = Wo + v;
#pragma unroll 1
    for (int k0 = 0; k0 < Hh; k0 += 4) {
        float w0 = Wp[(k0 + 0) * Vv];
        float w1 = Wp[(k0 + 1) * Vv];
        float w2 = Wp[(k0 + 2) * Vv];
        float w3 = Wp[(k0 + 3) * Vv];
        KB_STEP(k0 + 0, w0)
        KB_STEP(k0 + 1, w1)
        KB_STEP(k0 + 2, w2)
        KB_STEP(k0 + 3, w3)
    }

    float bo_v = bo[v];
    int lane = tid & 31, wz = tid >> 5;
    const unsigned FULL = 0xFFFFFFFFu;
    float* pred = out + PRED_OFF;

    // teacher rows 0..31 (pairs q=0..15)
#pragma unroll
    for (int q = 0; q < 16; ++q) {
        float l0, l1;
        unpack2(acc[q], l0, l1);
#pragma unroll
        for (int h = 0; h < 2; ++h) {
            int b = 2 * q + h;
            float logit = (h == 0 ? l0 : l1) + bo_v;
            pred[(b * Ss + t) * Vv + v] = logit;
            if (v == tgt_s[b]) atomicAdd(&g_loss, logit);
            float e = expf(logit);
            e += __shfl_down_sync(FULL, e, 16);
            e += __shfl_down_sync(FULL, e, 8);
            e += __shfl_down_sync(FULL, e, 4);
            e += __shfl_down_sync(FULL, e, 2);
            e += __shfl_down_sync(FULL, e, 1);
            if (lane == 0) wsum[wz][b] = e;
        }
    }
    // gen rows 32..63 (pairs q=16..31)
#pragma unroll
    for (int q = 16; q < 32; ++q) {
        float l0, l1;
        unpack2(acc[q], l0, l1);
#pragma unroll
        for (int h = 0; h < 2; ++h) {
            int r = 2 * q + h;
            float logit = (h == 0 ? l0 : l1) + bo_v;
            float e = expf(logit);
            e += __shfl_down_sync(FULL, e, 16);
            e += __shfl_down_sync(FULL, e, 8);
            e += __shfl_down_sync(FULL, e, 4);
            e += __shfl_down_sync(FULL, e, 2);
            e += __shfl_down_sync(FULL, e, 1);
            if (lane == 0) wsum[wz][r] = e;

            unsigned long long key =
                ((unsigned long long)f2ord(logit) << 32) |
                (unsigned long long)(0xFFFFFFFFu - (unsigned)v);
#pragma unroll
            for (int off = 16; off > 0; off >>= 1) {
                unsigned long long o = __shfl_down_sync(FULL, key, off);
                key = (o > key) ? o : key;
            }
            if (lane == 0) wkey[wz][r - Bb] = key;
        }
    }
    __syncthreads();

    if (tid < RR) {
        float s = wsum[0][tid] + wsum[1][tid] + wsum[2][tid] + wsum[3][tid];
        atomicAdd(&g_sumexp[t * RR + tid], s);
    } else if (tid < RR + Bb) {
        int gr = tid - RR;
        unsigned long long k0 = wkey[0][gr], k1 = wkey[1][gr];
        unsigned long long k2 = wkey[2][gr], k3 = wkey[3][gr];
        unsigned long long k = k0 > k1 ? k0 : k1;
        unsigned long long m = k2 > k3 ? k2 : k3;
        k = k > m ? k : m;
        atomicMax(&g_packmax[t * Bb + gr], k);
    }
}

// ---------------- epilogue 1: last gen outputs, loss, 1/sumexp -------------
__global__ void k_fin1(float* __restrict__ out) {
    __shared__ float red[1024];
    int tid = threadIdx.x;
    int t = tid >> 5, b = tid & 31;

    float se = g_sumexp[t * RR + b];            // teacher row b, step t
    red[tid] = logf(se);
    g_invse[b * Ss + t] = 1.0f / se;

    if (tid < Bb) {
        unsigned long long key = g_packmax[(Ss - 1) * Bb + tid];
        int tok = (int)(0xFFFFFFFFu - (unsigned)(key & 0xFFFFFFFFull));
        out[tid * Ss + (Ss - 1)] = (float)tok;
        float lg = ord2f((unsigned)(key >> 32));
        out[Bb * Ss + tid * Ss + (Ss - 1)] =
            expf(lg) / g_sumexp[(Ss - 1) * RR + Bb + tid];
    }
    __syncthreads();
    for (int s = 512; s > 0; s >>= 1) {
        if (tid < s) red[tid] += red[tid + s];
        __syncthreads();
    }
    if (tid == 0)
        out[PRED_OFF + PRED_N] = (red[0] - g_loss) / (float)(Ss * Bb);
}

// ---------------- epilogue 2: logits -> probs (in place, bulk) -------------
__global__ void k_probs(float* __restrict__ out) {
    int i = blockIdx.x * blockDim.x + threadIdx.x;       // 0 .. PRED_N/4-1
    int row = i / (Vv / 4);                              // = b*S + t
    float inv = g_invse[row];
    float4* p = ((float4*)(out + PRED_OFF)) + i;
    float4 l = *p;
    l.x = expf(l.x) * inv;
    l.y = expf(l.y) * inv;
    l.z = expf(l.z) * inv;
    l.w = expf(l.w) * inv;
    *p = l;
}

// ---------------- launch ---------------------------------------------------
extern "C" void kernel_launch(void* const* d_in, const int* in_sizes, int n_in,
                              void* d_out, int out_size) {
    const int*   x   = (const int*)d_in[0];
    const float* emb = (const float*)d_in[1];
    const float* Wi  = (const float*)d_in[2];
    const float* Ui  = (const float*)d_in[3];
    const float* bi  = (const float*)d_in[4];
    const float* Wf  = (const float*)d_in[5];
    const float* Uf  = (const float*)d_in[6];
    const float* bf  = (const float*)d_in[7];
    const float* Wog = (const float*)d_in[8];
    const float* Uog = (const float*)d_in[9];
    const float* bog = (const float*)d_in[10];
    const float* Wc  = (const float*)d_in[11];
    const float* Uc  = (const float*)d_in[12];
    const float* bc  = (const float*)d_in[13];
    const float* Wo  = (const float*)d_in[14];
    const float* bo  = (const float*)d_in[15];
    float* out = (float*)d_out;

    k_prologue<<<Ss * Bb, Hh>>>(x, emb, Wi, bi, Wf, bf, Wog, bog, Wc, bc);
    for (int t = 0; t < Ss; ++t) {
        k_cell<<<RR, Hh>>>(t, emb, Wi, Ui, bi, Wf, Uf, bf,
                           Wog, Uog, bog, Wc, Uc, bc, out);
        k_big<<<Vv / 128, 128>>>(t, x, Wo, bo, out);
    }
    k_fin1<<<1, 1024>>>(out);
    k_probs<<<PRED_N / (256 * 4), 256>>>(out);
}

// round 4
// speedup vs baseline: 1.6455x; 1.6455x over previous
#include <cuda_runtime.h>
#include <cstdint>

// Problem dims
#define Vv 32000
#define Ee 128
#define Hh 128
#define Bb 32
#define Ss 32
#define RR 64                  // 64 fused rows: 0..31 teacher, 32..63 generation
static const int PRED_OFF = 2048;           // gen_x[1024] + gen_o[1024]
static const int PRED_N   = Bb * Ss * Vv;   // 32,768,000

// ---------------- persistent device scratch (no allocations allowed) -------
__device__ float               g_h[RR * Hh];
__device__ float               g_c[RR * Hh];
__device__ float               g_xg[Ss * Bb * 4 * Hh];  // teacher x-gates (with bias)
__device__ float               g_sumexp[Ss * RR];
__device__ unsigned long long  g_packmax[Ss * Bb];
__device__ float               g_invse[Ss * Bb];        // indexed by b*S + t
__device__ float               g_loss;                  // sum of logit at target

// ---------------- helpers --------------------------------------------------
__device__ __forceinline__ float sigm(float x) { return 1.0f / (1.0f + expf(-x)); }

__device__ __forceinline__ unsigned f2ord(float f) {
    unsigned u = __float_as_uint(f);
    return (u & 0x80000000u) ? ~u : (u | 0x80000000u);
}
__device__ __forceinline__ float ord2f(unsigned o) {
    return __uint_as_float((o & 0x80000000u) ? (o ^ 0x80000000u) : ~o);
}

__device__ __forceinline__ unsigned long long fma2(unsigned long long a,
                                                   unsigned long long b,
                                                   unsigned long long c) {
    unsigned long long d;
    asm("fma.rn.f32x2 %0, %1, %2, %3;" : "=l"(d) : "l"(a), "l"(b), "l"(c));
    return d;
}
__device__ __forceinline__ unsigned long long pack2(float w) {
    unsigned long long d;
    unsigned u = __float_as_uint(w);
    asm("mov.b64 %0, {%1, %1};" : "=l"(d) : "r"(u));
    return d;
}
__device__ __forceinline__ void unpack2(unsigned long long a, float& lo, float& hi) {
    unsigned l, h;
    asm("mov.b64 {%0, %1}, %2;" : "=r"(l), "=r"(h) : "l"(a));
    lo = __uint_as_float(l);
    hi = __uint_as_float(h);
}

// ---------------- prologue: teacher-forced x-gate projections --------------
// 64 blocks x 512 threads; each block handles 16 (t,b) pairs with 16-way
// register blocking so each W element is loaded once per 16 tokens.
// xg[p][g*128+j] = b_g[j] + emb[tok] . W_g[:,j],  tok = t==0 ? START : x[b][t-1]
__global__ void __launch_bounds__(512)
k_prologue(const int* __restrict__ x, const float* __restrict__ emb,
           const float* __restrict__ Wi, const float* __restrict__ bi,
           const float* __restrict__ Wf, const float* __restrict__ bf,
           const float* __restrict__ Wog, const float* __restrict__ bog,
           const float* __restrict__ Wc, const float* __restrict__ bc) {
    int p0 = blockIdx.x * 16;
    int tid = threadIdx.x;
    int g = tid >> 7, j = tid & 127;

    __shared__ int   tok_s[16];
    __shared__ float xe[16][Ee];

    if (blockIdx.x == 0 && tid == 0) g_loss = 0.0f;
    if (tid < 16) {
        int p = p0 + tid;
        int t = p >> 5, b = p & 31;
        tok_s[tid] = (t == 0) ? 0 : x[b * Ss + (t - 1)];
    }
    __syncthreads();
    for (int idx = tid; idx < 16 * Ee; idx += 512) {
        int pp = idx >> 7, kk = idx & 127;
        xe[pp][kk] = emb[tok_s[pp] * Ee + kk];
    }
    __syncthreads();

    const float* W = (g == 0) ? Wi : (g == 1) ? Wf : (g == 2) ? Wog : Wc;
    float bias = ((g == 0) ? bi : (g == 1) ? bf : (g == 2) ? bog : bc)[j];

    float acc[16];
#pragma unroll
    for (int pp = 0; pp < 16; ++pp) acc[pp] = bias;

#pragma unroll 4
    for (int k = 0; k < Ee; ++k) {
        float w = W[k * Hh + j];
#pragma unroll
        for (int pp = 0; pp < 16; ++pp) acc[pp] += xe[pp][k] * w;
    }
#pragma unroll
    for (int pp = 0; pp < 16; ++pp)
        g_xg[(p0 + pp) * 4 * Hh + tid] = acc[pp];
}

// ---------------- per-step LSTM cell (64 rows) -----------------------------
// 512 threads/block: one thread per (gate g, column j). Each thread does at
// most 256 L2-hit loads (vs 1024 before), 16 warps/block hide the latency.
// Also: decodes previous step's argmax for gen rows (writes gen_x/gen_o[t-1]),
// and zero-inits this step's reduction accumulators.
__global__ void __launch_bounds__(512)
k_cell(int t, const float* __restrict__ emb,
       const float* __restrict__ Wi, const float* __restrict__ Ui, const float* __restrict__ bi,
       const float* __restrict__ Wf, const float* __restrict__ Uf, const float* __restrict__ bf,
       const float* __restrict__ Wog, const float* __restrict__ Uog, const float* __restrict__ bog,
       const float* __restrict__ Wc, const float* __restrict__ Uc, const float* __restrict__ bc,
       float* __restrict__ out) {
    int r = blockIdx.x;            // 0..63
    int tid = threadIdx.x;         // 0..511
    int g = tid >> 7, j = tid & 127;
    bool isgen = (r >= Bb);
    int b = isgen ? (r - Bb) : r;

    __shared__ float hsh[Hh];
    __shared__ float xe[Ee];
    __shared__ float gs[4 * Hh];

    if (tid == 0) {
        g_sumexp[t * RR + r] = 0.0f;
        if (isgen) g_packmax[t * Bb + b] = 0ull;
    }
    if (tid < Hh) hsh[tid] = (t == 0) ? 0.0f : g_h[r * Hh + tid];

    if (isgen) {
        int tok = 0;
        if (t > 0) {
            unsigned long long key = g_packmax[(t - 1) * Bb + b];
            tok = (int)(0xFFFFFFFFu - (unsigned)(key & 0xFFFFFFFFull));
            if (tid == 0) {
                float lg = ord2f((unsigned)(key >> 32));
                float se = g_sumexp[(t - 1) * RR + r];
                out[b * Ss + (t - 1)] = (float)tok;                 // gen_x
                out[Bb * Ss + b * Ss + (t - 1)] = expf(lg) / se;    // gen_o
            }
        }
        if (tid < Ee) xe[tid] = emb[tok * Ee + tid];
    }
    __syncthreads();

    const float* W = (g == 0) ? Wi : (g == 1) ? Wf : (g == 2) ? Wog : Wc;
    const float* U = (g == 0) ? Ui : (g == 1) ? Uf : (g == 2) ? Uog : Uc;

    float acc;
    if (isgen) {
        acc = ((g == 0) ? bi : (g == 1) ? bf : (g == 2) ? bog : bc)[j];
#pragma unroll 16
        for (int k = 0; k < Ee; ++k) acc += xe[k] * W[k * Hh + j];
    } else {
        acc = g_xg[(t * Bb + b) * 4 * Hh + tid];   // bias already folded in
    }
    if (t > 0) {
#pragma unroll 16
        for (int k = 0; k < Hh; ++k) acc += hsh[k] * U[k * Hh + j];
    }
    gs[tid] = acc;
    __syncthreads();

    if (tid < Hh) {
        float cprev = (t == 0) ? 0.0f : g_c[r * Hh + tid];
        float ig = sigm(gs[tid]);
        float fg = sigm(gs[Hh + tid]);
        float og = sigm(gs[2 * Hh + tid]);
        float cn = fg * cprev + ig * tanhf(gs[3 * Hh + tid]);
        float hn = og * tanhf(cn);
        g_h[r * Hh + tid] = hn;
        g_c[r * Hh + tid] = cn;
    }
}

// ---------------- per-step output GEMM + reductions ------------------------
// logits[r][v] = h[r] . Wo[:,v] + bo[v] for all 64 rows.
// Teacher rows: logit stored into pred region (converted to prob at the end),
//   exp summed per row (atomicAdd), logit-at-target summed into g_loss.
// Gen rows: exp summed per row, packed (logit,idx) max per row (atomicMax).
#define KB_STEP(KK, WREG)                                                       \
    {                                                                           \
        const ulonglong2* hp = (const ulonglong2*)(&h_s[(KK)][0]);              \
        unsigned long long ww = pack2(WREG);                                    \
        _Pragma("unroll")                                                       \
        for (int p = 0; p < 16; ++p) {                                          \
            ulonglong2 hv = hp[p];                                              \
            acc[2 * p]     = fma2(hv.x, ww, acc[2 * p]);                        \
            acc[2 * p + 1] = fma2(hv.y, ww, acc[2 * p + 1]);                    \
        }                                                                       \
    }

__global__ void __launch_bounds__(128, 2)
k_big(int t, const int* __restrict__ x, const float* __restrict__ Wo,
      const float* __restrict__ bo, float* __restrict__ out) {
    __shared__ float h_s[Hh][68];   // transposed h, padded (68*4 % 16 == 0)
    __shared__ float wsum[4][RR];
    __shared__ unsigned long long wkey[4][Bb];
    __shared__ int tgt_s[Bb];

    int tid = threadIdx.x;
    int v = blockIdx.x * 128 + tid;

    for (int it = 0; it < RR; ++it)
        h_s[tid][it] = g_h[it * Hh + tid];   // coalesced read, transpose write
    if (tid < Bb) tgt_s[tid] = x[tid * Ss + t];
    __syncthreads();

    unsigned long long acc[32];
#pragma unroll
    for (int p = 0; p < 32; ++p) acc[p] = 0ull;

    const float* Wp = Wo + v;
#pragma unroll 1
    for (int k0 = 0; k0 < Hh; k0 += 4) {
        float w0 = Wp[(k0 + 0) * Vv];
        float w1 = Wp[(k0 + 1) * Vv];
        float w2 = Wp[(k0 + 2) * Vv];
        float w3 = Wp[(k0 + 3) * Vv];
        KB_STEP(k0 + 0, w0)
        KB_STEP(k0 + 1, w1)
        KB_STEP(k0 + 2, w2)
        KB_STEP(k0 + 3, w3)
    }

    float bo_v = bo[v];
    int lane = tid & 31, wz = tid >> 5;
    const unsigned FULL = 0xFFFFFFFFu;
    float* pred = out + PRED_OFF;

    // teacher rows 0..31 (pairs q=0..15)
#pragma unroll
    for (int q = 0; q < 16; ++q) {
        float l0, l1;
        unpack2(acc[q], l0, l1);
#pragma unroll
        for (int h = 0; h < 2; ++h) {
            int b = 2 * q + h;
            float logit = (h == 0 ? l0 : l1) + bo_v;
            pred[(b * Ss + t) * Vv + v] = logit;
            if (v == tgt_s[b]) atomicAdd(&g_loss, logit);
            float e = expf(logit);
            e += __shfl_down_sync(FULL, e, 16);
            e += __shfl_down_sync(FULL, e, 8);
            e += __shfl_down_sync(FULL, e, 4);
            e += __shfl_down_sync(FULL, e, 2);
            e += __shfl_down_sync(FULL, e, 1);
            if (lane == 0) wsum[wz][b] = e;
        }
    }
    // gen rows 32..63 (pairs q=16..31)
#pragma unroll
    for (int q = 16; q < 32; ++q) {
        float l0, l1;
        unpack2(acc[q], l0, l1);
#pragma unroll
        for (int h = 0; h < 2; ++h) {
            int r = 2 * q + h;
            float logit = (h == 0 ? l0 : l1) + bo_v;
            float e = expf(logit);
            e += __shfl_down_sync(FULL, e, 16);
            e += __shfl_down_sync(FULL, e, 8);
            e += __shfl_down_sync(FULL, e, 4);
            e += __shfl_down_sync(FULL, e, 2);
            e += __shfl_down_sync(FULL, e, 1);
            if (lane == 0) wsum[wz][r] = e;

            unsigned long long key =
                ((unsigned long long)f2ord(logit) << 32) |
                (unsigned long long)(0xFFFFFFFFu - (unsigned)v);
#pragma unroll
            for (int off = 16; off > 0; off >>= 1) {
                unsigned long long o = __shfl_down_sync(FULL, key, off);
                key = (o > key) ? o : key;
            }
            if (lane == 0) wkey[wz][r - Bb] = key;
        }
    }
    __syncthreads();

    if (tid < RR) {
        float s = wsum[0][tid] + wsum[1][tid] + wsum[2][tid] + wsum[3][tid];
        atomicAdd(&g_sumexp[t * RR + tid], s);
    } else if (tid < RR + Bb) {
        int gr = tid - RR;
        unsigned long long k0 = wkey[0][gr], k1 = wkey[1][gr];
        unsigned long long k2 = wkey[2][gr], k3 = wkey[3][gr];
        unsigned long long k = k0 > k1 ? k0 : k1;
        unsigned long long m = k2 > k3 ? k2 : k3;
        k = k > m ? k : m;
        atomicMax(&g_packmax[t * Bb + gr], k);
    }
}

// ---------------- epilogue 1: last gen outputs, loss, 1/sumexp -------------
__global__ void k_fin1(float* __restrict__ out) {
    __shared__ float red[1024];
    int tid = threadIdx.x;
    int t = tid >> 5, b = tid & 31;

    float se = g_sumexp[t * RR + b];            // teacher row b, step t
    red[tid] = logf(se);
    g_invse[b * Ss + t] = 1.0f / se;

    if (tid < Bb) {
        unsigned long long key = g_packmax[(Ss - 1) * Bb + tid];
        int tok = (int)(0xFFFFFFFFu - (unsigned)(key & 0xFFFFFFFFull));
        out[tid * Ss + (Ss - 1)] = (float)tok;
        float lg = ord2f((unsigned)(key >> 32));
        out[Bb * Ss + tid * Ss + (Ss - 1)] =
            expf(lg) / g_sumexp[(Ss - 1) * RR + Bb + tid];
    }
    __syncthreads();
    for (int s = 512; s > 0; s >>= 1) {
        if (tid < s) red[tid] += red[tid + s];
        __syncthreads();
    }
    if (tid == 0)
        out[PRED_OFF + PRED_N] = (red[0] - g_loss) / (float)(Ss * Bb);
}

// ---------------- epilogue 2: logits -> probs (in place, bulk) -------------
__global__ void k_probs(float* __restrict__ out) {
    int i = blockIdx.x * blockDim.x + threadIdx.x;       // 0 .. PRED_N/4-1
    int row = i / (Vv / 4);                              // = b*S + t
    float inv = g_invse[row];
    float4* p = ((float4*)(out + PRED_OFF)) + i;
    float4 l = *p;
    l.x = expf(l.x) * inv;
    l.y = expf(l.y) * inv;
    l.z = expf(l.z) * inv;
    l.w = expf(l.w) * inv;
    *p = l;
}

// ---------------- launch ---------------------------------------------------
extern "C" void kernel_launch(void* const* d_in, const int* in_sizes, int n_in,
                              void* d_out, int out_size) {
    const int*   x   = (const int*)d_in[0];
    const float* emb = (const float*)d_in[1];
    const float* Wi  = (const float*)d_in[2];
    const float* Ui  = (const float*)d_in[3];
    const float* bi  = (const float*)d_in[4];
    const float* Wf  = (const float*)d_in[5];
    const float* Uf  = (const float*)d_in[6];
    const float* bf  = (const float*)d_in[7];
    const float* Wog = (const float*)d_in[8];
    const float* Uog = (const float*)d_in[9];
    const float* bog = (const float*)d_in[10];
    const float* Wc  = (const float*)d_in[11];
    const float* Uc  = (const float*)d_in[12];
    const float* bc  = (const float*)d_in[13];
    const float* Wo  = (const float*)d_in[14];
    const float* bo  = (const float*)d_in[15];
    float* out = (float*)d_out;

    k_prologue<<<Ss * Bb / 16, 512>>>(x, emb, Wi, bi, Wf, bf, Wog, bog, Wc, bc);
    for (int t = 0; t < Ss; ++t) {
        k_cell<<<RR, 512>>>(t, emb, Wi, Ui, bi, Wf, Uf, bf,
                            Wog, Uog, bog, Wc, Uc, bc, out);
        k_big<<<Vv / 128, 128>>>(t, x, Wo, bo, out);
    }
    k_fin1<<<1, 1024>>>(out);
    k_probs<<<PRED_N / (256 * 4), 256>>>(out);
}